// round 7
// baseline (speedup 1.0000x reference)
#include <cuda_runtime.h>

// LatentLinearModel: r[i] = dot(U[users[i]], V[jokes[i]]) + a[users[i]] + b[jokes[i]] + g
// B = 1048576, K = 64.
//
// Round 7: traffic reduction. R1-R6 showed we sit at the random-256B DRAM
// efficiency ceiling (~61% of peak) with ~291MB of traffic, ~94MB of which is
// duplicate U-row gathers whose L2 reuse distance is too long. Fix: counting-
// sort rows into 1024 buckets by user>>10 (256KB U windows), then run the
// proven R4-style cp.async gather kernel in permuted order. Duplicates and
// neighbors now hit L2; U DRAM traffic drops ~35%.
//
// Pipeline (all graph-capturable, scratch in __device__ globals):
//   memset hist -> histogram -> 1024-scan -> atomic scatter(perm) -> gather.
// out[row] is written per original row, so output is bitwise independent of
// the nondeterministic atomic ordering inside buckets.

#define TPR    16
#define RPG    4
#define BLOCK  256
#define GROUPS (BLOCK / TPR)
#define RPB    (GROUPS * RPG)      // 64 rows per tile
#define NB     1024                // buckets (user >> 10, N < 2^20)
#define CAP    (1 << 20)           // max B supported by perm scratch

__device__ int d_hist[NB];
__device__ int d_base[NB];
__device__ int d_perm[CAP];

__device__ __forceinline__ void cp_async16(void* smem, const void* gmem) {
    unsigned s = (unsigned)__cvta_generic_to_shared(smem);
    asm volatile("cp.async.cg.shared.global [%0], [%1], 16;" :: "r"(s), "l"(gmem));
}

// ---------------- pass 1: histogram of user>>10 ----------------
__global__ void __launch_bounds__(BLOCK)
hist_kernel(const int* __restrict__ users, int B) {
    __shared__ int sh[NB];
    for (int i = threadIdx.x; i < NB; i += BLOCK) sh[i] = 0;
    __syncthreads();
    for (int i = blockIdx.x * BLOCK + threadIdx.x; i < B; i += gridDim.x * BLOCK)
        atomicAdd(&sh[__ldg(&users[i]) >> 10], 1);
    __syncthreads();
    for (int i = threadIdx.x; i < NB; i += BLOCK) {
        int v = sh[i];
        if (v) atomicAdd(&d_hist[i], v);
    }
}

// ---------------- pass 2: exclusive scan of 1024 counters ----------------
__global__ void __launch_bounds__(NB)
scan_kernel() {
    __shared__ int s[NB];
    int t = threadIdx.x;
    int orig = d_hist[t];
    s[t] = orig;
    __syncthreads();
    for (int off = 1; off < NB; off <<= 1) {
        int v = (t >= off) ? s[t - off] : 0;
        __syncthreads();
        s[t] += v;
        __syncthreads();
    }
    d_base[t] = s[t] - orig;   // exclusive prefix; becomes the bucket cursor
}

// ---------------- pass 3: scatter row ids into bucket order ----------------
__global__ void __launch_bounds__(BLOCK)
scatter_kernel(const int* __restrict__ users, int B) {
    for (int i = blockIdx.x * BLOCK + threadIdx.x; i < B; i += gridDim.x * BLOCK) {
        int bkt = __ldg(&users[i]) >> 10;
        int pos = atomicAdd(&d_base[bkt], 1);
        d_perm[pos] = i;
    }
}

// ---------------- pass 4: R4-style gather over permuted rows ----------------
template <bool PERM>
__global__ void __launch_bounds__(BLOCK)
gather_kernel(const int* __restrict__ users,
              const int* __restrict__ jokes,
              const float4* __restrict__ U4,
              const float4* __restrict__ V4,
              const float* __restrict__ a,
              const float* __restrict__ b,
              const float* __restrict__ g,
              float* __restrict__ out,
              int B) {
    __shared__ float4 sU[RPB][TPR];   // 16 KB
    __shared__ float4 sV[RPB][TPR];   // 16 KB

    int lane  = threadIdx.x & (TPR - 1);
    int lrow0 = (threadIdx.x >> 4) * RPG;
    int row0  = blockIdx.x * RPB + lrow0;
    if (row0 >= B) return;

    // Row ids this group handles (permuted or natural).
    int pr[RPG];
    if (PERM) {
        if (row0 + RPG <= B) {
            int4 pv = *(const int4*)&d_perm[row0];   // row0 multiple of 4
            pr[0] = pv.x; pr[1] = pv.y; pr[2] = pv.z; pr[3] = pv.w;
        } else {
#pragma unroll
            for (int r = 0; r < RPG; r++)
                pr[r] = d_perm[(row0 + r < B) ? (row0 + r) : (B - 1)];
        }
    } else {
#pragma unroll
        for (int r = 0; r < RPG; r++)
            pr[r] = (row0 + r < B) ? (row0 + r) : (B - 1);
    }

    // Index gathers (users/jokes arrays are 4MB each -> L2 resident).
    int us[RPG], js[RPG];
#pragma unroll
    for (int r = 0; r < RPG; r++) us[r] = __ldg(&users[pr[r]]);
#pragma unroll
    for (int r = 0; r < RPG; r++) js[r] = __ldg(&jokes[pr[r]]);

    // Issue all 8 row-gathers as cp.async (in-flight bytes live in smem).
#pragma unroll
    for (int r = 0; r < RPG; r++) {
        cp_async16(&sU[lrow0 + r][lane], &U4[(size_t)us[r] * 16 + lane]);
        cp_async16(&sV[lrow0 + r][lane], &V4[(size_t)js[r] * 16 + lane]);
    }
    asm volatile("cp.async.commit_group;");

    // Bias loads fly concurrently (lane 0 only).
    float bias[RPG];
    if (lane == 0) {
#pragma unroll
        for (int r = 0; r < RPG; r++)
            bias[r] = __ldg(&a[us[r]]) + __ldg(&b[js[r]]);
    }
    float gg = __ldg(&g[0]);

    asm volatile("cp.async.wait_group 0;" ::: "memory");

#pragma unroll
    for (int r = 0; r < RPG; r++) {
        float4 uu = sU[lrow0 + r][lane];
        float4 vv = sV[lrow0 + r][lane];
        float d = uu.x * vv.x + uu.y * vv.y + uu.z * vv.z + uu.w * vv.w;
        d += __shfl_xor_sync(0xffffffffu, d, 8);
        d += __shfl_xor_sync(0xffffffffu, d, 4);
        d += __shfl_xor_sync(0xffffffffu, d, 2);
        d += __shfl_xor_sync(0xffffffffu, d, 1);
        if (lane == 0 && row0 + r < B) {
            out[pr[r]] = d + bias[r] + gg;
        }
    }
}

extern "C" void kernel_launch(void* const* d_in, const int* in_sizes, int n_in,
                              void* d_out, int out_size) {
    // metadata order: users, jokes, U, V, a, b, g
    const int*    users = (const int*)d_in[0];
    const int*    jokes = (const int*)d_in[1];
    const float4* U4    = (const float4*)d_in[2];
    const float4* V4    = (const float4*)d_in[3];
    const float*  a     = (const float*)d_in[4];
    const float*  b     = (const float*)d_in[5];
    const float*  g     = (const float*)d_in[6];
    float* out = (float*)d_out;

    int B = in_sizes[0];
    int grid = (B + RPB - 1) / RPB;

    if (B <= CAP) {
        void* hist_ptr = nullptr;
        cudaGetSymbolAddress(&hist_ptr, d_hist);
        cudaMemsetAsync(hist_ptr, 0, NB * sizeof(int));
        hist_kernel<<<512, BLOCK>>>(users, B);
        scan_kernel<<<1, NB>>>();
        scatter_kernel<<<1024, BLOCK>>>(users, B);
        gather_kernel<true><<<grid, BLOCK>>>(users, jokes, U4, V4, a, b, g, out, B);
    } else {
        gather_kernel<false><<<grid, BLOCK>>>(users, jokes, U4, V4, a, b, g, out, B);
    }
}

// round 8
// speedup vs baseline: 2.5537x; 2.5537x over previous
#include <cuda_runtime.h>

// LatentLinearModel: r[i] = dot(U[users[i]], V[jokes[i]]) + a[users[i]] + b[jokes[i]] + g
// B = 1048576, K = 64.
//
// Round 8: revert to the proven R4 structure (one-shot blocks, cp.async
// gathers into smem, 8 outstanding 16B gathers per thread) and add
// L2::evict_last cache policy on the U/V gathers. ~368K of the 1M U-row
// gathers are duplicates (B=1M draws over N=1M users); with evict_last the
// fetched 256B rows linger in the 126MB L2, so a fraction of the duplicate
// re-gathers hit L2 instead of re-reading DRAM. No reordering: all 4B
// streams (indices, out) stay perfectly coalesced (R7 lesson).

#define TPR    16                   // threads per row
#define RPG    4                    // rows per 16-lane group
#define BLOCK  256
#define GROUPS (BLOCK / TPR)        // 16
#define RPB    (GROUPS * RPG)       // 64 rows per block

__device__ __forceinline__ void cp_async16_policy(void* smem, const void* gmem,
                                                  unsigned long long policy) {
    unsigned s = (unsigned)__cvta_generic_to_shared(smem);
    asm volatile("cp.async.cg.shared.global.L2::cache_hint [%0], [%1], 16, %2;"
                 :: "r"(s), "l"(gmem), "l"(policy));
}

__global__ void __launch_bounds__(BLOCK)
latent_linear_kernel(const int* __restrict__ users,
                     const int* __restrict__ jokes,
                     const float4* __restrict__ U4,
                     const float4* __restrict__ V4,
                     const float* __restrict__ a,
                     const float* __restrict__ b,
                     const float* __restrict__ g,
                     float* __restrict__ out,
                     int B) {
    __shared__ float4 sU[RPB][TPR];   // 16 KB
    __shared__ float4 sV[RPB][TPR];   // 16 KB

    int lane  = threadIdx.x & (TPR - 1);
    int group = threadIdx.x >> 4;
    int lrow0 = group * RPG;                       // local row base in smem
    int row0  = blockIdx.x * RPB + lrow0;          // global row base
    if (row0 >= B) return;

    // L2 evict_last policy: keep gathered rows resident so duplicate
    // user-row gathers later in the launch hit L2.
    unsigned long long policy;
    asm("createpolicy.fractional.L2::evict_last.b64 %0, 1.0;" : "=l"(policy));

    // ---- Phase 1: vectorized index loads (row0 multiple of 4 -> 16B aligned) ----
    int4 ui = __ldg((const int4*)(users + row0));
    int4 ji = __ldg((const int4*)(jokes + row0));
    int us[RPG] = {ui.x, ui.y, ui.z, ui.w};
    int js[RPG] = {ji.x, ji.y, ji.z, ji.w};

    // ---- Phase 2: issue all 8 gathers per thread as cp.async (no reg cost) ----
#pragma unroll
    for (int r = 0; r < RPG; r++) {
        cp_async16_policy(&sU[lrow0 + r][lane], &U4[(size_t)us[r] * 16 + lane], policy);
        cp_async16_policy(&sV[lrow0 + r][lane], &V4[(size_t)js[r] * 16 + lane], policy);
    }
    asm volatile("cp.async.commit_group;");

    // Bias loads fly concurrently with the cp.asyncs (lane 0 only).
    float bias[RPG];
    if (lane == 0) {
#pragma unroll
        for (int r = 0; r < RPG; r++) {
            bias[r] = __ldg(&a[us[r]]) + __ldg(&b[js[r]]);
        }
    }
    float gg = __ldg(&g[0]);

    asm volatile("cp.async.wait_group 0;" ::: "memory");

    // ---- Phase 3: dot + 16-lane reduction per row (thread-private smem slots) ----
#pragma unroll
    for (int r = 0; r < RPG; r++) {
        float4 uu = sU[lrow0 + r][lane];
        float4 vv = sV[lrow0 + r][lane];
        float d = uu.x * vv.x + uu.y * vv.y + uu.z * vv.z + uu.w * vv.w;
        d += __shfl_xor_sync(0xffffffffu, d, 8);
        d += __shfl_xor_sync(0xffffffffu, d, 4);
        d += __shfl_xor_sync(0xffffffffu, d, 2);
        d += __shfl_xor_sync(0xffffffffu, d, 1);
        if (lane == 0) {
            out[row0 + r] = d + bias[r] + gg;
        }
    }
}

extern "C" void kernel_launch(void* const* d_in, const int* in_sizes, int n_in,
                              void* d_out, int out_size) {
    // metadata order: users, jokes, U, V, a, b, g
    const int*    users = (const int*)d_in[0];
    const int*    jokes = (const int*)d_in[1];
    const float4* U4    = (const float4*)d_in[2];
    const float4* V4    = (const float4*)d_in[3];
    const float*  a     = (const float*)d_in[4];
    const float*  b     = (const float*)d_in[5];
    const float*  g     = (const float*)d_in[6];
    float* out = (float*)d_out;

    int B = in_sizes[0];

    int grid = (B + RPB - 1) / RPB;
    latent_linear_kernel<<<grid, BLOCK>>>(users, jokes, U4, V4, a, b, g, out, B);
}